// round 7
// baseline (speedup 1.0000x reference)
#include <cuda_runtime.h>

// out[b, f] = x0[b, f] * dot(x[b,:], w) + bias[f] + x[b, f]
// B = 16384 rows, F = 2048 cols, fp32.
//
// R7: 2 rows per CTA, 512 threads (1 float4 per stream per row per thread).
// Rationale: all prior variants plateau at DRAM 81-83% (~6.5 TB/s) -- the
// mixed read/write turnaround ceiling. This batches DRAM traffic into
// longer same-direction bursts: 6 front-batched LDG.128 per thread (32 KB
// contiguous reads per CTA), then 2 back-to-back STG.128 (16 KB contiguous
// writes), half the barriers and half the CTA scheduling events per byte.

#define F_DIM 2048
#define VEC_PER_ROW (F_DIM / 4)   // 512 float4
#define THREADS 512
#define NWARPS (THREADS / 32)     // 16
#define ROWS_PER_CTA 2

__global__ __launch_bounds__(THREADS)
void cross_fused2_kernel(const float4* __restrict__ x0,
                         const float4* __restrict__ x,
                         const float4* __restrict__ w,
                         const float4* __restrict__ bias,
                         float4* __restrict__ out)
{
    const int tid  = threadIdx.x;
    const long r0  = (long)blockIdx.x * ROWS_PER_CTA;
    const long i0  = r0 * VEC_PER_ROW + tid;          // row 0, this thread's lane
    const long i1  = i0 + VEC_PER_ROW;                // row 1, same lane

    // Front-batched reads: 6 LDG.128 in flight per thread.
    float4 xa  = x[i0];
    float4 xb  = x[i1];
    float4 x0a = x0[i0];
    float4 x0b = x0[i1];
    float4 wa  = w[tid];
    float4 ba  = bias[tid];

    // Per-thread partial dots for both rows.
    float sa = xa.x * wa.x + xa.y * wa.y + xa.z * wa.z + xa.w * wa.w;
    float sb = xb.x * wa.x + xb.y * wa.y + xb.z * wa.z + xb.w * wa.w;

    // Precompute (bias + x) for both rows before the barrier.
    float4 pa, pb;
    pa.x = ba.x + xa.x;  pa.y = ba.y + xa.y;
    pa.z = ba.z + xa.z;  pa.w = ba.w + xa.w;
    pb.x = ba.x + xb.x;  pb.y = ba.y + xb.y;
    pb.z = ba.z + xb.z;  pb.w = ba.w + xb.w;

    // Warp reduce both sums (interleaved, independent chains).
    #pragma unroll
    for (int off = 16; off > 0; off >>= 1) {
        sa += __shfl_xor_sync(0xFFFFFFFFu, sa, off);
        sb += __shfl_xor_sync(0xFFFFFFFFu, sb, off);
    }

    // Single barrier for both rows' cross-warp reduces.
    __shared__ float warp_sums[2][NWARPS];
    const int lane = tid & 31;
    const int warp = tid >> 5;
    if (lane == 0) {
        warp_sums[0][warp] = sa;
        warp_sums[1][warp] = sb;
    }
    __syncthreads();

    float xwa = 0.0f, xwb = 0.0f;
    #pragma unroll
    for (int i = 0; i < NWARPS; i++) {
        xwa += warp_sums[0][i];   // broadcast LDS
        xwb += warp_sums[1][i];
    }

    // out = x0 * xw + (bias + x), both rows, stores back-to-back.
    float4 oa, ob;
    oa.x = fmaf(x0a.x, xwa, pa.x);
    oa.y = fmaf(x0a.y, xwa, pa.y);
    oa.z = fmaf(x0a.z, xwa, pa.z);
    oa.w = fmaf(x0a.w, xwa, pa.w);
    ob.x = fmaf(x0b.x, xwb, pb.x);
    ob.y = fmaf(x0b.y, xwb, pb.y);
    ob.z = fmaf(x0b.z, xwb, pb.z);
    ob.w = fmaf(x0b.w, xwb, pb.w);

    out[i0] = oa;
    out[i1] = ob;
}

extern "C" void kernel_launch(void* const* d_in, const int* in_sizes, int n_in,
                              void* d_out, int out_size)
{
    const float4* x0   = (const float4*)d_in[0];
    const float4* x    = (const float4*)d_in[1];
    const float4* w    = (const float4*)d_in[2];
    const float4* bias = (const float4*)d_in[3];
    float4* out = (float4*)d_out;

    const int rows = in_sizes[0] / F_DIM;              // 16384
    const int grid = rows / ROWS_PER_CTA;              // 8192
    cross_fused2_kernel<<<grid, THREADS>>>(x0, x, w, bias, out);
}

// round 8
// speedup vs baseline: 1.0406x; 1.0406x over previous
#include <cuda_runtime.h>

// out[b, f] = x0[b, f] * dot(x[b,:], w) + bias[f] + x[b, f]
// B = 16384 rows, F = 2048 cols, fp32. One CTA per row, 256 threads,
// each thread owns 8 columns (2 x float4).
//
// FINAL (R8 = R1 profile minus one barrier):
//  - 32 regs / occ 8 CTAs-per-SM pinned via __launch_bounds__(256, 8):
//    across 7 measured variants, the 32-reg high-occupancy shape gives the
//    best WALL time (61.5us) even though the 38-reg front-batched shape
//    profiles faster under ncu -- in the timed replay loop occupancy wins.
//  - x / w loaded first (dot-critical path); x0 / bias issued around the
//    reduce where ptxas places them under the 32-reg budget.
//  - Single __syncthreads: lane 0 publishes warp partials, every thread
//    sums all 8 via broadcast LDS (saves R1's second barrier).
//  - Default cache policy; ldcs/stcs, persistence, 512-thr, 2-rows/CTA all
//    measured neutral-or-worse. Kernel is pinned at the HBM3e mixed R/W
//    ceiling (~6.5 TB/s, DRAM 81-83%) with irreducible 384 MiB traffic.

#define F_DIM 2048
#define VEC_PER_ROW (F_DIM / 4)   // 512 float4
#define THREADS 256
#define NWARPS (THREADS / 32)

__global__ __launch_bounds__(THREADS, 8)
void cross_fused_kernel(const float4* __restrict__ x0,
                        const float4* __restrict__ x,
                        const float4* __restrict__ w,
                        const float4* __restrict__ bias,
                        float4* __restrict__ out)
{
    const int row = blockIdx.x;
    const int tid = threadIdx.x;
    const long base = (long)row * VEC_PER_ROW;

    const int i0 = tid;
    const int i1 = tid + THREADS;

    // Dot-critical loads first.
    float4 xa = x[base + i0];
    float4 xb = x[base + i1];
    float4 wa = w[i0];
    float4 wb = w[i1];

    // Per-thread partial dot.
    float s = xa.x * wa.x + xa.y * wa.y + xa.z * wa.z + xa.w * wa.w
            + xb.x * wb.x + xb.y * wb.y + xb.z * wb.z + xb.w * wb.w;

    // Warp reduce.
    #pragma unroll
    for (int off = 16; off > 0; off >>= 1)
        s += __shfl_xor_sync(0xFFFFFFFFu, s, off);

    // Single-barrier cross-warp reduce: lane 0 publishes, everyone sums.
    __shared__ float warp_sums[NWARPS];
    const int lane = tid & 31;
    const int warp = tid >> 5;
    if (lane == 0) warp_sums[warp] = s;
    __syncthreads();

    float xw = 0.0f;
    #pragma unroll
    for (int i = 0; i < NWARPS; i++)
        xw += warp_sums[i];   // broadcast LDS, conflict-free

    // Epilogue loads (placed by ptxas within the 32-reg budget).
    float4 x0a = x0[base + i0];
    float4 x0b = x0[base + i1];
    float4 ba  = bias[i0];
    float4 bb  = bias[i1];

    // out = x0 * xw + bias + x
    float4 oa, ob;
    oa.x = fmaf(x0a.x, xw, ba.x + xa.x);
    oa.y = fmaf(x0a.y, xw, ba.y + xa.y);
    oa.z = fmaf(x0a.z, xw, ba.z + xa.z);
    oa.w = fmaf(x0a.w, xw, ba.w + xa.w);
    ob.x = fmaf(x0b.x, xw, bb.x + xb.x);
    ob.y = fmaf(x0b.y, xw, bb.y + xb.y);
    ob.z = fmaf(x0b.z, xw, bb.z + xb.z);
    ob.w = fmaf(x0b.w, xw, bb.w + xb.w);

    out[base + i0] = oa;
    out[base + i1] = ob;
}

extern "C" void kernel_launch(void* const* d_in, const int* in_sizes, int n_in,
                              void* d_out, int out_size)
{
    const float4* x0   = (const float4*)d_in[0];
    const float4* x    = (const float4*)d_in[1];
    const float4* w    = (const float4*)d_in[2];
    const float4* bias = (const float4*)d_in[3];
    float4* out = (float4*)d_out;

    const int rows = in_sizes[0] / F_DIM;  // 16384
    cross_fused_kernel<<<rows, THREADS>>>(x0, x, w, bias, out);
}